// round 1
// baseline (speedup 1.0000x reference)
#include <cuda_runtime.h>
#include <cstdint>

// Batched GEMM: C[b] = A[b] (1024x64) @ B[b] (64x1024), b in [0,24), fp32.
// Strategy: 128x128 CTA tile, BK=32 (K=64 in two chunks), 256 threads,
// 8x8 per-thread micro-tile using packed fma.rn.f32x2 (FFMA2) accumulators.

#define BM 128
#define BN 128
#define BK 32
#define TM 8
#define TN 8

#define M_DIM 1024
#define N_DIM 1024
#define K_DIM 64
#define BATCH 24

__device__ __forceinline__ unsigned long long splat_f32x2(float x) {
    unsigned long long r;
    asm("mov.b64 %0, {%1, %1};" : "=l"(r) : "f"(x));
    return r;
}

__device__ __forceinline__ void fma_f32x2(unsigned long long& d,
                                          unsigned long long a,
                                          unsigned long long b) {
    asm("fma.rn.f32x2 %0, %1, %2, %0;" : "+l"(d) : "l"(a), "l"(b));
}

__device__ __forceinline__ void unpack_f32x2(unsigned long long v, float& lo, float& hi) {
    asm("mov.b64 {%0, %1}, %2;" : "=f"(lo), "=f"(hi) : "l"(v));
}

__global__ void __launch_bounds__(256)
bmm_f32x2_kernel(const float* __restrict__ A,
                 const float* __restrict__ B,
                 float* __restrict__ C) {
    // As is stored TRANSPOSED: As[k][m]. +1 pad makes the transpose store
    // (lanes vary in both k and m) conflict-free, and the compute-phase reads
    // of As[k][m] are 2-address broadcasts (only 2 distinct ty per warp).
    __shared__ float As[BK][BM + 1];
    __shared__ float Bs[BK][BN];

    const int tid = threadIdx.x;
    const int tx = tid & 15;   // n-direction thread coord (16)
    const int ty = tid >> 4;   // m-direction thread coord (16)

    const int bz = blockIdx.z;
    const int row0 = blockIdx.y * BM;
    const int col0 = blockIdx.x * BN;

    const float* __restrict__ Ab = A + (long long)bz * M_DIM * K_DIM;
    const float* __restrict__ Bb = B + (long long)bz * K_DIM * N_DIM;
    float*       __restrict__ Cb = C + (long long)bz * M_DIM * N_DIM;

    // 8 m-rows x 4 n-pairs of packed f32x2 accumulators (64 regs)
    unsigned long long acc[TM][TN / 2];
#pragma unroll
    for (int i = 0; i < TM; i++)
#pragma unroll
        for (int j = 0; j < TN / 2; j++) acc[i][j] = 0ULL;  // (0.0f, 0.0f)

    // Per-thread A-load coords: each thread loads 4 float4s (one per 32-row group)
    const int a_r  = tid >> 3;        // 0..31 base row within tile
    const int a_c4 = (tid & 7) * 4;   // k-offset within chunk: 0,4,...,28

    for (int kk = 0; kk < K_DIM; kk += BK) {
        // ---- Load A chunk [128 rows x 32 k] and transpose into As[k][m] ----
#pragma unroll
        for (int i = 0; i < 4; i++) {
            const int row = a_r + i * 32;
            float4 v = *reinterpret_cast<const float4*>(
                &Ab[(long long)(row0 + row) * K_DIM + kk + a_c4]);
            As[a_c4 + 0][row] = v.x;
            As[a_c4 + 1][row] = v.y;
            As[a_c4 + 2][row] = v.z;
            As[a_c4 + 3][row] = v.w;
        }
        // ---- Load B chunk [32 k x 128 n] ----
#pragma unroll
        for (int i = 0; i < 4; i++) {
            const int f  = tid + i * 256;   // float4 index 0..1023
            const int kr = f >> 5;          // 0..31
            const int nc = (f & 31) * 4;    // 0..124
            float4 v = *reinterpret_cast<const float4*>(
                &Bb[(long long)(kk + kr) * N_DIM + col0 + nc]);
            *reinterpret_cast<float4*>(&Bs[kr][nc]) = v;
        }
        __syncthreads();

        // ---- Compute: 32 k-steps, 8x8 micro-tile via FFMA2 ----
#pragma unroll
        for (int k = 0; k < BK; k++) {
            // B fragment: 8 floats = 4 packed pairs (32B-aligned in smem)
            unsigned long long bp[4];
            {
                const ulonglong2 q0 = *reinterpret_cast<const ulonglong2*>(&Bs[k][tx * TN]);
                const ulonglong2 q1 = *reinterpret_cast<const ulonglong2*>(&Bs[k][tx * TN + 4]);
                bp[0] = q0.x; bp[1] = q0.y; bp[2] = q1.x; bp[3] = q1.y;
            }
#pragma unroll
            for (int i = 0; i < TM; i++) {
                const unsigned long long ap = splat_f32x2(As[k][ty * TM + i]);
                fma_f32x2(acc[i][0], ap, bp[0]);
                fma_f32x2(acc[i][1], ap, bp[1]);
                fma_f32x2(acc[i][2], ap, bp[2]);
                fma_f32x2(acc[i][3], ap, bp[3]);
            }
        }
        __syncthreads();
    }

    // ---- Epilogue: unpack pairs, two float4 stores per m-row ----
#pragma unroll
    for (int i = 0; i < TM; i++) {
        const long long off =
            (long long)(row0 + ty * TM + i) * N_DIM + col0 + tx * TN;
        float4 o0, o1;
        unpack_f32x2(acc[i][0], o0.x, o0.y);
        unpack_f32x2(acc[i][1], o0.z, o0.w);
        unpack_f32x2(acc[i][2], o1.x, o1.y);
        unpack_f32x2(acc[i][3], o1.z, o1.w);
        *reinterpret_cast<float4*>(&Cb[off])     = o0;
        *reinterpret_cast<float4*>(&Cb[off + 4]) = o1;
    }
}

extern "C" void kernel_launch(void* const* d_in, const int* in_sizes, int n_in,
                              void* d_out, int out_size) {
    const float* A = (const float*)d_in[0];   // x1: [2,12,1024,64]
    const float* B = (const float*)d_in[1];   // x2: [2,12,64,1024]
    // d_in[2], d_in[3] (clip_val1/2) are unused in the forward reference.
    float* C = (float*)d_out;                 // [2,12,1024,1024] fp32

    dim3 grid(N_DIM / BN, M_DIM / BM, BATCH); // (8, 8, 24)
    dim3 block(256);
    bmm_f32x2_kernel<<<grid, block>>>(A, B, C);
}

// round 3
// speedup vs baseline: 2.0883x; 2.0883x over previous
#include <cuda_runtime.h>
#include <cuda_bf16.h>
#include <cstdint>

// C[b] = A[b](1024x64) @ B[b](64x1024), fp32, b in [0,24).
// mma.sync bf16 (m16n8k16) with 2-term bf16 split: acc = a0b0 + a0b1 + a1b0.
// CTA tile 128x128, full K=64 in smem. 256 threads = 8 warps, warp tile 32x64.

#define M_DIM 1024
#define N_DIM 1024
#define K_DIM 64
#define BATCH 24
#define BM 128
#define BN 128
#define THREADS 256

// smem: 4 tiles of 128 rows x 64 bf16 (= 128B/row, SW128-swizzled), 16 KB each
#define SMEM_A0 0
#define SMEM_A1 16384
#define SMEM_B0 32768
#define SMEM_B1 49152
#define SMEM_TOTAL 65536

#define SW128(o) ((o) ^ (((o) >> 3) & 0x70))

__device__ __forceinline__ uint32_t smem_u32(const void* p) {
    uint32_t a;
    asm("{ .reg .u64 t; cvta.to.shared.u64 t, %1; cvt.u32.u64 %0, t; }"
        : "=r"(a) : "l"(p));
    return a;
}

__device__ __forceinline__ void ldsm_x4(uint32_t* r, uint32_t addr) {
    asm volatile("ldmatrix.sync.aligned.m8n8.x4.shared.b16 {%0,%1,%2,%3}, [%4];"
                 : "=r"(r[0]), "=r"(r[1]), "=r"(r[2]), "=r"(r[3])
                 : "r"(addr));
}

__device__ __forceinline__ void mma_bf16(float* c, const uint32_t* a,
                                         uint32_t b0, uint32_t b1) {
    asm volatile(
        "mma.sync.aligned.m16n8k16.row.col.f32.bf16.bf16.f32 "
        "{%0,%1,%2,%3}, {%4,%5,%6,%7}, {%8,%9}, {%0,%1,%2,%3};"
        : "+f"(c[0]), "+f"(c[1]), "+f"(c[2]), "+f"(c[3])
        : "r"(a[0]), "r"(a[1]), "r"(a[2]), "r"(a[3]), "r"(b0), "r"(b1));
}

__device__ __forceinline__ uint32_t pack2(__nv_bfloat16 lo, __nv_bfloat16 hi) {
    return (uint32_t)__bfloat16_as_ushort(lo) |
           ((uint32_t)__bfloat16_as_ushort(hi) << 16);
}

__device__ __forceinline__ void split_bf16(float v, __nv_bfloat16& h, __nv_bfloat16& l) {
    h = __float2bfloat16(v);
    l = __float2bfloat16(v - __bfloat162float(h));
}

__global__ void __launch_bounds__(THREADS)
bmm_hmma_kernel(const float* __restrict__ A,
                const float* __restrict__ B,
                float* __restrict__ C) {
    extern __shared__ __align__(1024) char smem[];
    const uint32_t smem_base = smem_u32(smem);
    const int tid = threadIdx.x;
    const int wid = tid >> 5;
    const int lid = tid & 31;

    const int bz   = blockIdx.z;
    const int row0 = blockIdx.y * BM;
    const int col0 = blockIdx.x * BN;

    const float* __restrict__ Ab = A + (size_t)bz * M_DIM * K_DIM;
    const float* __restrict__ Bb = B + (size_t)bz * K_DIM * N_DIM;
    float*       __restrict__ Cb = C + (size_t)bz * M_DIM * N_DIM;

    // ---- A tile: [128 m][64 k] fp32 -> bf16 hi/lo smem (row-major, SW128) ----
    // 2048 float4s, 8 per thread. f: r = f>>4 (row), q = f&15 (k quad).
#pragma unroll
    for (int i = 0; i < 8; i++) {
        const int f = tid + i * THREADS;
        const int r = f >> 4;
        const int q = f & 15;
        float4 v = *reinterpret_cast<const float4*>(
            &Ab[(size_t)(row0 + r) * K_DIM + q * 4]);
        __nv_bfloat16 hx, lx, hy, ly, hz, lz, hw, lw;
        split_bf16(v.x, hx, lx); split_bf16(v.y, hy, ly);
        split_bf16(v.z, hz, lz); split_bf16(v.w, hw, lw);
        uint2 hi = make_uint2(pack2(hx, hy), pack2(hz, hw));
        uint2 lo = make_uint2(pack2(lx, ly), pack2(lz, lw));
        const uint32_t off = SW128((uint32_t)(r * 128 + q * 8));
        *reinterpret_cast<uint2*>(smem + SMEM_A0 + off) = hi;
        *reinterpret_cast<uint2*>(smem + SMEM_A1 + off) = lo;
    }

    // ---- B tile: global [64 k][128 n] -> smem BT[n][k] bf16 hi/lo ----
    // Thread owns column n = tid&127 for k-half (tid>>7)*32; 4 groups of 8 k's.
    {
        const int n  = tid & 127;
        const int kh = (tid >> 7) * 32;
        const float* bcol = Bb + col0 + n;
#pragma unroll
        for (int k8 = 0; k8 < 4; k8++) {
            float v[8];
#pragma unroll
            for (int j = 0; j < 8; j++)
                v[j] = bcol[(size_t)(kh + k8 * 8 + j) * N_DIM];
            __nv_bfloat16 h[8], l[8];
#pragma unroll
            for (int j = 0; j < 8; j++) split_bf16(v[j], h[j], l[j]);
            uint4 hi, lo;
            hi.x = pack2(h[0], h[1]); hi.y = pack2(h[2], h[3]);
            hi.z = pack2(h[4], h[5]); hi.w = pack2(h[6], h[7]);
            lo.x = pack2(l[0], l[1]); lo.y = pack2(l[2], l[3]);
            lo.z = pack2(l[4], l[5]); lo.w = pack2(l[6], l[7]);
            const uint32_t off = SW128((uint32_t)(n * 128 + (kh + k8 * 8) * 2));
            *reinterpret_cast<uint4*>(smem + SMEM_B0 + off) = hi;
            *reinterpret_cast<uint4*>(smem + SMEM_B1 + off) = lo;
        }
    }

    __syncthreads();

    // ---- warp tiling: warp_m = wid%4 (32 rows), warp_n = wid/4 (64 cols) ----
    const int warp_m = wid & 3;
    const int warp_n = wid >> 2;

    // ldmatrix per-lane address pieces
    const int g = lid >> 3;
    const int r8 = lid & 7;
    // A x4: rows (g&1)*8 + r8 within 16-row frag; k-halves (g>>1)*16 bytes
    const int a_row_l = warp_m * 32 + (g & 1) * 8 + r8;
    const int a_kb_l  = (g >> 1) * 16;
    // B x4: n rows (g>>1)*8 + r8 within 16-n group; k-halves (g&1)*16 bytes
    const int b_row_l = warp_n * 64 + (g >> 1) * 8 + r8;
    const int b_kb_l  = (g & 1) * 16;

    float acc[2][8][4];
#pragma unroll
    for (int mi = 0; mi < 2; mi++)
#pragma unroll
        for (int ni = 0; ni < 8; ni++)
#pragma unroll
            for (int j = 0; j < 4; j++) acc[mi][ni][j] = 0.0f;

    // 3 passes: (A0,B0), (A0,B1), (A1,B0)
#pragma unroll
    for (int p = 0; p < 3; p++) {
        const uint32_t abase = smem_base + (p < 2 ? SMEM_A0 : SMEM_A1);
        const uint32_t bbase = smem_base + (p == 1 ? SMEM_B1 : SMEM_B0);
#pragma unroll
        for (int ks = 0; ks < 4; ks++) {
            uint32_t afrag[2][4];
#pragma unroll
            for (int mi = 0; mi < 2; mi++) {
                const uint32_t off =
                    (uint32_t)((a_row_l + mi * 16) * 128 + ks * 32 + a_kb_l);
                ldsm_x4(afrag[mi], abase + SW128(off));
            }
            uint32_t bfrag[8][2];
#pragma unroll
            for (int nq = 0; nq < 4; nq++) {
                uint32_t rr[4];
                const uint32_t off =
                    (uint32_t)((b_row_l + nq * 16) * 128 + ks * 32 + b_kb_l);
                ldsm_x4(rr, bbase + SW128(off));
                bfrag[nq * 2 + 0][0] = rr[0]; bfrag[nq * 2 + 0][1] = rr[1];
                bfrag[nq * 2 + 1][0] = rr[2]; bfrag[nq * 2 + 1][1] = rr[3];
            }
#pragma unroll
            for (int mi = 0; mi < 2; mi++)
#pragma unroll
                for (int ni = 0; ni < 8; ni++)
                    mma_bf16(acc[mi][ni], afrag[mi], bfrag[ni][0], bfrag[ni][1]);
        }
    }

    // ---- epilogue: direct stores. Per frag: thread holds c[r][(q)*2..+1] and r+8. ----
    const int tq = lid & 3;   // quad lane -> 2 cols
    const int tr = lid >> 2;  // row within 8-row group
#pragma unroll
    for (int mi = 0; mi < 2; mi++) {
        const int rbase = row0 + warp_m * 32 + mi * 16 + tr;
        float* c0 = &Cb[(size_t)rbase * N_DIM + col0 + warp_n * 64 + tq * 2];
        float* c1 = c0 + 8 * N_DIM;
#pragma unroll
        for (int ni = 0; ni < 8; ni++) {
            float2 v0 = make_float2(acc[mi][ni][0], acc[mi][ni][1]);
            float2 v1 = make_float2(acc[mi][ni][2], acc[mi][ni][3]);
            *reinterpret_cast<float2*>(c0 + ni * 8) = v0;
            *reinterpret_cast<float2*>(c1 + ni * 8) = v1;
        }
    }
}

extern "C" void kernel_launch(void* const* d_in, const int* in_sizes, int n_in,
                              void* d_out, int out_size) {
    const float* A = (const float*)d_in[0];   // [2,12,1024,64]
    const float* B = (const float*)d_in[1];   // [2,12,64,1024]
    float* C = (float*)d_out;                 // [2,12,1024,1024]

    cudaFuncSetAttribute(bmm_hmma_kernel,
                         cudaFuncAttributeMaxDynamicSharedMemorySize, SMEM_TOTAL);
    dim3 grid(N_DIM / BN, M_DIM / BM, BATCH);  // (8, 8, 24)
    bmm_hmma_kernel<<<grid, THREADS, SMEM_TOTAL>>>(A, B, C);
}